// round 3
// baseline (speedup 1.0000x reference)
#include <cuda_runtime.h>
#include <cuda_bf16.h>

// Problem constants (match reference setup_inputs)
#define B    4096
#define S    200
#define E    300
#define TAGS 2
#define EV4  (E / 4)     // 75 float4 per embedding row

#define BM   16          // batch rows per CTA
#define NT   256         // threads per CTA
#define NPAD 301         // row stride for pooled/h1 smem (conflict-free: 301%32=13, odd)
#define NW   320         // padded N for W tiles / w3 (16 groups x 20)
#define BK   12          // k-tile
#define NKT  25          // 300 / 12

// ---------------------------------------------------------------------------
// One k-sweep of C[m, n0..n0+19] = sum_k A_s[m][k] * Wg[n][k]  (W row-major [N,K])
// W tiles streamed global->regs->smem (transposed), double-buffered in regs.
// All threads must call (uniform barriers).
// ---------------------------------------------------------------------------
__device__ __forceinline__ void gemm300(
    const float* __restrict__ Wg,
    const float* __restrict__ s_a,
    float*                     s_w,
    int m, int n0, int tid, float acc[20])
{
#pragma unroll
    for (int j = 0; j < 20; ++j) acc[j] = 0.f;

    float4 pf[4];
    // prefetch tile 0 (k0 = 0)
#pragma unroll
    for (int i = 0; i < 4; ++i) {
        const int idx = tid + i * NT;
        pf[i] = make_float4(0.f, 0.f, 0.f, 0.f);
        if (idx < NW * 3) {
            const int n = idx / 3, slot = idx % 3;
            if (n < E) pf[i] = *(const float4*)&Wg[n * E + slot * 4];
        }
    }

    for (int kt = 0; kt < NKT; ++kt) {
        __syncthreads();   // previous consumers of s_w / writers of s_a are done
        // store prefetched tile (transposed: s_w[k][n])
#pragma unroll
        for (int i = 0; i < 4; ++i) {
            const int idx = tid + i * NT;
            if (idx < NW * 3) {
                const int n = idx / 3, slot = idx % 3;
                s_w[(slot * 4 + 0) * NW + n] = pf[i].x;
                s_w[(slot * 4 + 1) * NW + n] = pf[i].y;
                s_w[(slot * 4 + 2) * NW + n] = pf[i].z;
                s_w[(slot * 4 + 3) * NW + n] = pf[i].w;
            }
        }
        // prefetch next tile (overlaps with compute below)
        if (kt + 1 < NKT) {
            const int k0n = (kt + 1) * BK;
#pragma unroll
            for (int i = 0; i < 4; ++i) {
                const int idx = tid + i * NT;
                pf[i] = make_float4(0.f, 0.f, 0.f, 0.f);
                if (idx < NW * 3) {
                    const int n = idx / 3, slot = idx % 3;
                    if (n < E) pf[i] = *(const float4*)&Wg[n * E + k0n + slot * 4];
                }
            }
        }
        __syncthreads();

        const int k0 = kt * BK;
#pragma unroll
        for (int kk = 0; kk < BK; ++kk) {
            const float a = s_a[m * NPAD + k0 + kk];          // broadcast, conflict-free
            const float4* wr = (const float4*)(s_w + kk * NW + n0);  // broadcast per half-warp
#pragma unroll
            for (int j = 0; j < 5; ++j) {
                const float4 w = wr[j];
                acc[j * 4 + 0] = fmaf(a, w.x, acc[j * 4 + 0]);
                acc[j * 4 + 1] = fmaf(a, w.y, acc[j * 4 + 1]);
                acc[j * 4 + 2] = fmaf(a, w.z, acc[j * 4 + 2]);
                acc[j * 4 + 3] = fmaf(a, w.w, acc[j * 4 + 3]);
            }
        }
    }
}

// ---------------------------------------------------------------------------
// Fully fused: gather+mean-pool -> relu(xW1^T) -> relu(hW2^T) -> hW3^T
// One CTA handles 16 batch rows end-to-end.
// ---------------------------------------------------------------------------
__global__ __launch_bounds__(NT, 2) void fused_all(
    const int*   __restrict__ x,
    const float* __restrict__ emb,
    const float* __restrict__ w1,
    const float* __restrict__ w2,
    const float* __restrict__ w3,
    float*       __restrict__ out)
{
    __shared__ float s_buf[BK * NW];        // union: token ids (3200 ints) / W tile
    __shared__ float s_a[BM * NPAD];        // pooled, later h1
    __shared__ float s_w3[TAGS * NW];
    __shared__ float s_part[BM * 16 * 2];

    const int tid = threadIdx.x;
    const int b0  = blockIdx.x * BM;
    int* s_ids = (int*)s_buf;

    // --- load token ids (contiguous 3200 ints) + padded w3 ---
    {
        const int4* src = (const int4*)(x + b0 * S);
        int4* dst = (int4*)s_ids;
        for (int i = tid; i < BM * S / 4; i += NT) dst[i] = src[i];
    }
    for (int i = tid; i < TAGS * NW; i += NT) {
        const int t = i / NW, n = i % NW;
        s_w3[i] = (n < E) ? w3[t * E + n] : 0.f;
    }
    __syncthreads();

    // --- gather + mean pool: warp w owns rows 2w, 2w+1 ---
    {
        const int warp = tid >> 5, lane = tid & 31;
        const int m0 = warp * 2, m1 = m0 + 1;
        const float4* __restrict__ ev = (const float4*)emb;
        const bool has2 = lane < (EV4 - 64);   // lanes 0..10 own slot lane+64

        float4 a00 = {0,0,0,0}, a01 = {0,0,0,0}, a02 = {0,0,0,0};
        float4 a10 = {0,0,0,0}, a11 = {0,0,0,0}, a12 = {0,0,0,0};

#pragma unroll 2
        for (int t = 0; t < S; ++t) {
            const int i0 = s_ids[m0 * S + t] * EV4;   // <= 37.5M, fits int
            const int i1 = s_ids[m1 * S + t] * EV4;
            float4 v;
            v = __ldg(ev + i0 + lane);        a00.x += v.x; a00.y += v.y; a00.z += v.z; a00.w += v.w;
            v = __ldg(ev + i0 + lane + 32);   a01.x += v.x; a01.y += v.y; a01.z += v.z; a01.w += v.w;
            v = __ldg(ev + i1 + lane);        a10.x += v.x; a10.y += v.y; a10.z += v.z; a10.w += v.w;
            v = __ldg(ev + i1 + lane + 32);   a11.x += v.x; a11.y += v.y; a11.z += v.z; a11.w += v.w;
            if (has2) {
                v = __ldg(ev + i0 + lane + 64); a02.x += v.x; a02.y += v.y; a02.z += v.z; a02.w += v.w;
                v = __ldg(ev + i1 + lane + 64); a12.x += v.x; a12.y += v.y; a12.z += v.z; a12.w += v.w;
            }
        }
        const float sc = 1.0f / (float)S;
        float* p0 = s_a + m0 * NPAD;
        float* p1 = s_a + m1 * NPAD;
        const int d0 = 4 * lane, d1 = 4 * (lane + 32), d2 = 4 * (lane + 64);
        p0[d0+0] = a00.x*sc; p0[d0+1] = a00.y*sc; p0[d0+2] = a00.z*sc; p0[d0+3] = a00.w*sc;
        p0[d1+0] = a01.x*sc; p0[d1+1] = a01.y*sc; p0[d1+2] = a01.z*sc; p0[d1+3] = a01.w*sc;
        p1[d0+0] = a10.x*sc; p1[d0+1] = a10.y*sc; p1[d0+2] = a10.z*sc; p1[d0+3] = a10.w*sc;
        p1[d1+0] = a11.x*sc; p1[d1+1] = a11.y*sc; p1[d1+2] = a11.z*sc; p1[d1+3] = a11.w*sc;
        if (has2) {
            p0[d2+0] = a02.x*sc; p0[d2+1] = a02.y*sc; p0[d2+2] = a02.z*sc; p0[d2+3] = a02.w*sc;
            p1[d2+0] = a12.x*sc; p1[d2+1] = a12.y*sc; p1[d2+2] = a12.z*sc; p1[d2+3] = a12.w*sc;
        }
    }
    // (gemm300 begins with __syncthreads: ids reads & pooled writes are fenced there)

    const int m  = tid & 15;     // batch row within tile
    const int g  = tid >> 4;     // n-group
    const int n0 = g * 20;

    float acc[20];

    // --- layer 1: h1 = relu(pooled @ W1^T) ---
    gemm300(w1, s_a, s_buf, m, n0, tid, acc);
    __syncthreads();             // all reads of pooled done before overwrite
#pragma unroll
    for (int j = 0; j < 20; ++j) {
        const int n = n0 + j;
        if (n < E) s_a[m * NPAD + n] = fmaxf(acc[j], 0.f);
    }

    // --- layer 2 + fused head ---
    gemm300(w2, s_a, s_buf, m, n0, tid, acc);

    float s0 = 0.f, s1 = 0.f;
#pragma unroll
    for (int j = 0; j < 20; ++j) {
        const float v = fmaxf(acc[j], 0.f);      // pad cols: acc=0 -> contributes 0
        s0 = fmaf(v, s_w3[n0 + j],      s0);
        s1 = fmaf(v, s_w3[NW + n0 + j], s1);
    }
    s_part[(m * 16 + g) * 2 + 0] = s0;
    s_part[(m * 16 + g) * 2 + 1] = s1;
    __syncthreads();

    if (tid < 32) {
        const int mm = tid >> 1, t = tid & 1;
        float s = 0.f;
#pragma unroll
        for (int gg = 0; gg < 16; ++gg)
            s += s_part[(mm * 16 + gg) * 2 + t];
        out[(b0 + mm) * TAGS + t] = s;
    }
}

// ---------------------------------------------------------------------------
// Launch
// inputs (metadata order): x [B*S] int32, emb [VOCAB*E] f32,
//                          w1 [E*E] f32, w2 [E*E] f32, w3 [TAGS*E] f32
// output: [B*TAGS] f32
// ---------------------------------------------------------------------------
extern "C" void kernel_launch(void* const* d_in, const int* in_sizes, int n_in,
                              void* d_out, int out_size)
{
    const int*   x   = (const int*)d_in[0];
    const float* emb = (const float*)d_in[1];
    const float* w1  = (const float*)d_in[2];
    const float* w2  = (const float*)d_in[3];
    const float* w3  = (const float*)d_in[4];
    float* out = (float*)d_out;

    fused_all<<<B / BM, NT>>>(x, emb, w1, w2, w3, out);
}

// round 4
// speedup vs baseline: 1.0866x; 1.0866x over previous
#include <cuda_runtime.h>
#include <cstdint>

// Problem constants
#define B    4096
#define S    200
#define E    300
#define TAGS 2
#define EV4  75          // float4 per embedding row

#define BM   8           // batch rows per CTA
#define NT   256         // threads per CTA
#define NPAD 301         // smem row stride for pooled/h1 (conflict-free)
#define NW   320         // padded N for transposed weights (32 groups x 10)
#define BK   10          // k-tile
#define NKT  30          // 300 / 10
#define TILE_F4 (BK * NW / 4)   // 800 float4 per W tile

// Pre-transposed, padded weights: wt[k*NW + n] = w[n*E + k] (0 for n>=E)
__device__ float g_w1t[E * NW];
__device__ float g_w2t[E * NW];

__global__ __launch_bounds__(256) void transpose_pad(
    const float* __restrict__ w, float* __restrict__ wt)
{
    const int idx = blockIdx.x * 256 + threadIdx.x;
    if (idx < E * NW) {
        const int k = idx / NW, n = idx % NW;
        wt[idx] = (n < E) ? w[n * E + k] : 0.0f;
    }
}

__device__ __forceinline__ void cp16(uint32_t saddr, const void* gptr)
{
    asm volatile("cp.async.cg.shared.global [%0], [%1], 16;"
                 :: "r"(saddr), "l"(gptr));
}
__device__ __forceinline__ void cp_commit()
{
    asm volatile("cp.async.commit_group;");
}

// ---------------------------------------------------------------------------
// One layer: acc[j] = sum_k s_a[m][k] * Wt[k][n0+j], Wt pretransposed [300][320].
// Double-buffered cp.async tile pipeline. All threads must call.
// ---------------------------------------------------------------------------
__device__ __forceinline__ void gemmT(
    const float* __restrict__ Wt,
    const float* __restrict__ s_a,
    float (*s_w)[BK * NW],
    int m, int n0, int tid, float acc[10])
{
#pragma unroll
    for (int j = 0; j < 10; ++j) acc[j] = 0.0f;

    const uint32_t sb0 = (uint32_t)__cvta_generic_to_shared(&s_w[0][0]);
    const uint32_t sb1 = (uint32_t)__cvta_generic_to_shared(&s_w[1][0]);

    // prologue: tile 0 -> buf 0
#pragma unroll
    for (int i = 0; i < 4; ++i) {
        const int idx = tid + i * NT;
        if (idx < TILE_F4) cp16(sb0 + idx * 16, Wt + idx * 4);
    }
    cp_commit();

    for (int kt = 0; kt < NKT; ++kt) {
        // issue tile kt+1 into buf (kt+1)&1
        if (kt + 1 < NKT) {
            const uint32_t dst = ((kt + 1) & 1) ? sb1 : sb0;
            const float* src = Wt + (kt + 1) * BK * NW;
#pragma unroll
            for (int i = 0; i < 4; ++i) {
                const int idx = tid + i * NT;
                if (idx < TILE_F4) cp16(dst + idx * 16, src + idx * 4);
            }
            cp_commit();
            asm volatile("cp.async.wait_group 1;");
        } else {
            asm volatile("cp.async.wait_group 0;");
        }
        __syncthreads();   // tile kt visible to all

        const float* wb = s_w[kt & 1];
        const int kb = kt * BK;
#pragma unroll
        for (int kk = 0; kk < BK; ++kk) {
            const float a = s_a[m * NPAD + kb + kk];
            const float2* wr = (const float2*)(wb + kk * NW + n0);
#pragma unroll
            for (int j = 0; j < 5; ++j) {
                const float2 w = wr[j];
                acc[2 * j + 0] = fmaf(a, w.x, acc[2 * j + 0]);
                acc[2 * j + 1] = fmaf(a, w.y, acc[2 * j + 1]);
            }
        }
        __syncthreads();   // compute on buf kt done before it is re-filled
    }
}

// ---------------------------------------------------------------------------
// Fused: gather+mean-pool -> relu(xW1^T) -> relu(hW2^T) -> hW3^T
// One CTA = 8 batch rows. grid = 512 -> ~3.5 CTAs/SM resident.
// ---------------------------------------------------------------------------
__global__ __launch_bounds__(NT, 4) void fused_all(
    const int*   __restrict__ x,
    const float* __restrict__ emb,
    const float* __restrict__ w1t,
    const float* __restrict__ w2t,
    const float* __restrict__ w3,
    float*       __restrict__ out)
{
    __shared__ float s_w[2][BK * NW];      // W tiles; buf1 aliases token ids
    __shared__ float s_a[BM * NPAD];       // pooled, later h1
    __shared__ float s_w3[TAGS * NW];
    __shared__ float s_part[BM * 32 * 2];

    const int tid = threadIdx.x;
    const int b0  = blockIdx.x * BM;
    int* s_ids = (int*)s_w[1];             // 1600 ints = 6.4KB <= 12.8KB

    // --- token ids (contiguous) + padded w3 ---
    {
        const int4* src = (const int4*)(x + b0 * S);
        int4* dst = (int4*)s_ids;
#pragma unroll
        for (int i = 0; i < 2; ++i) {
            const int idx = tid + i * NT;
            if (idx < BM * S / 4) dst[idx] = src[idx];
        }
    }
#pragma unroll
    for (int i = 0; i < 3; ++i) {
        const int idx = tid + i * NT;
        if (idx < TAGS * NW) {
            const int t = idx / NW, n = idx % NW;
            s_w3[idx] = (n < E) ? w3[t * E + n] : 0.0f;
        }
    }
    __syncthreads();

    // --- gather + mean pool: warp w owns batch row w ---
    {
        const int w = tid >> 5, lane = tid & 31;
        const bool has2 = lane < (EV4 - 64);     // lanes 0..10 own slot lane+64
        const float4* __restrict__ ev = (const float4*)emb;
        const int* __restrict__ rid = s_ids + w * S;

        float4 a0 = {0,0,0,0}, a1 = {0,0,0,0}, a2 = {0,0,0,0};
#pragma unroll 4
        for (int t = 0; t < S; ++t) {
            const int base = rid[t] * EV4;       // <= 37.5M, fits int32
            float4 v0 = __ldg(ev + base + lane);
            float4 v1 = __ldg(ev + base + lane + 32);
            a0.x += v0.x; a0.y += v0.y; a0.z += v0.z; a0.w += v0.w;
            a1.x += v1.x; a1.y += v1.y; a1.z += v1.z; a1.w += v1.w;
            if (has2) {
                float4 v2 = __ldg(ev + base + lane + 64);
                a2.x += v2.x; a2.y += v2.y; a2.z += v2.z; a2.w += v2.w;
            }
        }
        const float sc = 1.0f / (float)S;
        float* p = s_a + w * NPAD;
        const int d0 = 4 * lane, d1 = 4 * (lane + 32), d2 = 4 * (lane + 64);
        p[d0+0] = a0.x*sc; p[d0+1] = a0.y*sc; p[d0+2] = a0.z*sc; p[d0+3] = a0.w*sc;
        p[d1+0] = a1.x*sc; p[d1+1] = a1.y*sc; p[d1+2] = a1.z*sc; p[d1+3] = a1.w*sc;
        if (has2) {
            p[d2+0] = a2.x*sc; p[d2+1] = a2.y*sc; p[d2+2] = a2.z*sc; p[d2+3] = a2.w*sc;
        }
    }
    __syncthreads();   // ids reads & pooled writes done before buf1 refill / compute

    const int m  = tid & 7;     // batch row
    const int g  = tid >> 3;    // n-group (0..31)
    const int n0 = g * 10;

    float acc[10];

    // --- layer 1: h1 = relu(pooled @ W1^T) ---
    gemmT(w1t, s_a, s_w, m, n0, tid, acc);
    // gemmT ends with __syncthreads: all reads of pooled complete
#pragma unroll
    for (int j = 0; j < 10; ++j) {
        const int n = n0 + j;
        if (n < E) s_a[m * NPAD + n] = fmaxf(acc[j], 0.0f);
    }
    // h1 writes fenced by the first __syncthreads inside the next gemmT

    // --- layer 2 + fused head ---
    gemmT(w2t, s_a, s_w, m, n0, tid, acc);

    float s0 = 0.0f, s1 = 0.0f;
#pragma unroll
    for (int j = 0; j < 10; ++j) {
        const float v = fmaxf(acc[j], 0.0f);    // pad cols give 0
        s0 = fmaf(v, s_w3[n0 + j],      s0);
        s1 = fmaf(v, s_w3[NW + n0 + j], s1);
    }
    s_part[(m * 32 + g) * 2 + 0] = s0;
    s_part[(m * 32 + g) * 2 + 1] = s1;
    __syncthreads();

    if (tid < BM * TAGS) {
        const int mm = tid >> 1, t = tid & 1;
        float s = 0.0f;
#pragma unroll
        for (int gg = 0; gg < 32; ++gg)
            s += s_part[(mm * 32 + gg) * 2 + t];
        out[(b0 + mm) * TAGS + t] = s;
    }
}

// ---------------------------------------------------------------------------
// Launch
// ---------------------------------------------------------------------------
extern "C" void kernel_launch(void* const* d_in, const int* in_sizes, int n_in,
                              void* d_out, int out_size)
{
    const int*   x   = (const int*)d_in[0];
    const float* emb = (const float*)d_in[1];
    const float* w1  = (const float*)d_in[2];
    const float* w2  = (const float*)d_in[3];
    const float* w3  = (const float*)d_in[4];
    float* out = (float*)d_out;

    float* w1t; cudaGetSymbolAddress((void**)&w1t, g_w1t);
    float* w2t; cudaGetSymbolAddress((void**)&w2t, g_w2t);

    const int tgrid = (E * NW + 255) / 256;
    transpose_pad<<<tgrid, 256>>>(w1, w1t);
    transpose_pad<<<tgrid, 256>>>(w2, w2t);

    fused_all<<<B / BM, NT>>>(x, emb, w1t, w2t, w3, out);
}